// round 14
// baseline (speedup 1.0000x reference)
#include <cuda_runtime.h>
#include <cuda_bf16.h>
#include <cstdint>

// SequenceEmbedding: out[0][c][i][j] = one_hot(seq[i])[c]          for c in [0,4)
//                    out[0][c][i][j] = one_hot(seq[j])[c-4]        for c in [4,8)
// Output (1, 8, 4096, 4096) fp32 = 536.9 MB of pure stores.
//
// R12 = R11 retry with legal encoding: sm_103 ptxas requires 256-bit stores
// (.v8.b32) for L2::evict_last. Early blocks (~first 412 MB) stream out with
// evict-first (__stcs); tail blocks (last ~100 MB, executed last) store with
// evict_last so their dirty lines stay in L2 past kernel end and never cost
// in-kernel HBM writeback. Floor model: (537MB - resident_tail)/HBM_write.

#define SEQ_L   4096
#define NB      4
#define ROWS_PB 8           // rows per block -> 128 KB per block
#define TPB     256
#define EL_THRESH 3300      // blocks >= this (last ~99.5 MB) use evict_last

__device__ __forceinline__ bool seq_is_int64(const int* s32) {
    bool is64 = true;
#pragma unroll
    for (int k = 0; k < 64; k++) {
        if (s32[2 * k + 1] != 0) is64 = false;
    }
    return is64;
}

__device__ __forceinline__ int seq_at(const void* seq, int i, bool is64) {
    if (is64) return (int)((const long long*)seq)[i];
    return ((const int*)seq)[i];
}

// 256-bit evict_last store (the only width ptxas accepts for this hint).
__device__ __forceinline__ void st_el_256(float4* p, float4 a, float4 b) {
    asm volatile(
        "st.global.L2::evict_last.v8.b32 [%0], {%1,%2,%3,%4,%5,%6,%7,%8};"
        :: "l"(p),
           "r"(__float_as_uint(a.x)), "r"(__float_as_uint(a.y)),
           "r"(__float_as_uint(a.z)), "r"(__float_as_uint(a.w)),
           "r"(__float_as_uint(b.x)), "r"(__float_as_uint(b.y)),
           "r"(__float_as_uint(b.z)), "r"(__float_as_uint(b.w))
        : "memory");
}

// Store a 32B chunk: evict_last (tail) or evict-first pair (early).
__device__ __forceinline__ void st_chunk(float4* p, float4 a, float4 b, bool el) {
    if (el) {
        st_el_256(p, a, b);
    } else {
        __stcs(p, a);
        __stcs(p + 1, b);
    }
}

__global__ void __launch_bounds__(TPB, 6)
SequenceEmbedding_30923764532139_kernel(const void* __restrict__ seq,
                                        const float* __restrict__ bt,
                                        float* __restrict__ out) {
    const int bx = blockIdx.x;
    const int c  = bx >> 9;                // 512 blocks per channel, 8 channels
    const int i0 = (bx & 511) * ROWS_PB;   // first row handled by this block
    const int t  = threadIdx.x;
    const bool el = (bx >= EL_THRESH);     // tail blocks: keep lines in L2

    const bool is64 = seq_is_int64((const int*)seq);

    float4* __restrict__ chan = (float4*)(out + (size_t)c * SEQ_L * SEQ_L);
    const int row_f4 = SEQ_L / 4;          // 1024 float4 per row (512 x 32B chunks)

    if (c < NB) {
        // Row-splat channels: value constant along j, varies per row i.
#pragma unroll
        for (int r = 0; r < ROWS_PB; r++) {
            const int i = i0 + r;
            const float v = bt[seq_at(seq, i, is64) * NB + c];   // uniform, L1-hot
            const float4 vv = make_float4(v, v, v, v);
            float4* rowp = chan + (size_t)i * row_f4;
            // Two 32B chunks per thread: chunk indices t and t+256.
#pragma unroll
            for (int k = 0; k < 2; k++) {
                st_chunk(rowp + 2 * (t + k * TPB), vv, vv, el);
            }
        }
    } else {
        // Column-pattern channels: every row of the channel is identical.
        // p[2k],p[2k+1] form the 32B chunk at index (t + k*TPB).
        const int cc = c - NB;
        float4 p[4];
#pragma unroll
        for (int k = 0; k < 4; k++) {
            const int base = 8 * t + (k & 1) * 4 + (k >> 1) * 8 * TPB;
            p[k].x = bt[seq_at(seq, base + 0, is64) * NB + cc];
            p[k].y = bt[seq_at(seq, base + 1, is64) * NB + cc];
            p[k].z = bt[seq_at(seq, base + 2, is64) * NB + cc];
            p[k].w = bt[seq_at(seq, base + 3, is64) * NB + cc];
        }
#pragma unroll
        for (int r = 0; r < ROWS_PB; r++) {
            float4* rowp = chan + (size_t)(i0 + r) * row_f4;
#pragma unroll
            for (int k = 0; k < 2; k++) {
                st_chunk(rowp + 2 * (t + k * TPB), p[2 * k], p[2 * k + 1], el);
            }
        }
    }
}

extern "C" void kernel_launch(void* const* d_in, const int* in_sizes, int n_in,
                              void* d_out, int out_size) {
    const void*  seq = d_in[0];                 // 4096 ids (int32 or int64; auto-detected)
    const float* bt  = (const float*)d_in[1];   // 4x4 table, fp32
    float*       out = (float*)d_out;           // (1, 8, 4096, 4096) fp32

    const int total_rows = 8 * SEQ_L;                    // 32768
    const int grid = total_rows / ROWS_PB;               // 4096 blocks
    SequenceEmbedding_30923764532139_kernel<<<grid, TPB>>>(seq, bt, out);
}

// round 15
// speedup vs baseline: 1.5118x; 1.5118x over previous
#include <cuda_runtime.h>
#include <cuda_bf16.h>
#include <cstdint>

// SequenceEmbedding: out[0][c][i][j] = one_hot(seq[i])[c]          for c in [0,4)
//                    out[0][c][i][j] = one_hot(seq[j])[c-4]        for c in [4,8)
// Output (1, 8, 4096, 4096) fp32 = 536.9 MB of pure stores; HBM-write-bound.
//
// R14 = champion lock-in (exact R6 config, best measured 80.0us).
// Experiment series established the plateau: wave shape (R3), occupancy
// (R4), evict hints (R6/R12), and the TMA store path (R7/R10) all converge
// at ~6.6 TB/s wall store rate — the LTS/HBM write ceiling, path-independent.
// 4096 blocks x 8 rows, 256 thr, 6 blocks/SM, STG.128 evict-first streams.

#define SEQ_L   4096
#define NB      4
#define ROWS_PB 8           // rows per block
#define TPB     256         // threads per block

// Detect whether seq buffer is int64 or int32 (values in [0,4): odd 32-bit
// words of an int64 LE layout are all zero; FP prob 4^-64 for int32 data).
__device__ __forceinline__ bool seq_is_int64(const int* s32) {
    bool is64 = true;
#pragma unroll
    for (int k = 0; k < 64; k++) {
        if (s32[2 * k + 1] != 0) is64 = false;
    }
    return is64;
}

__device__ __forceinline__ int seq_at(const void* seq, int i, bool is64) {
    if (is64) return (int)((const long long*)seq)[i];
    return ((const int*)seq)[i];
}

__global__ void __launch_bounds__(TPB, 6)
SequenceEmbedding_30923764532139_kernel(const void* __restrict__ seq,
                                        const float* __restrict__ bt,
                                        float* __restrict__ out) {
    const int bx = blockIdx.x;
    const int c  = bx >> 9;                // 512 blocks per channel, 8 channels
    const int i0 = (bx & 511) * ROWS_PB;   // first row handled by this block
    const int t  = threadIdx.x;

    const bool is64 = seq_is_int64((const int*)seq);

    float4* __restrict__ chan = (float4*)(out + (size_t)c * SEQ_L * SEQ_L);
    const int row_f4 = SEQ_L / 4;          // 1024 float4 per row

    if (c < NB) {
        // Row-splat channels: value constant along j, varies per row i.
#pragma unroll
        for (int r = 0; r < ROWS_PB; r++) {
            const int i = i0 + r;
            const float v = bt[seq_at(seq, i, is64) * NB + c];   // uniform, L1-hot
            const float4 vv = make_float4(v, v, v, v);
            float4* rowp = chan + (size_t)i * row_f4;
#pragma unroll
            for (int k = 0; k < 4; k++) {
                __stcs(rowp + t + k * TPB, vv);   // warp-contiguous 512B streaming stores
            }
        }
    } else {
        // Column-pattern channels: every row of the channel is identical.
        // Materialize this thread's 16 pattern floats once; replay 8 rows.
        const int cc = c - NB;
        float4 p[4];
#pragma unroll
        for (int k = 0; k < 4; k++) {
            const int j = 4 * (t + k * TPB);
            p[k].x = bt[seq_at(seq, j + 0, is64) * NB + cc];
            p[k].y = bt[seq_at(seq, j + 1, is64) * NB + cc];
            p[k].z = bt[seq_at(seq, j + 2, is64) * NB + cc];
            p[k].w = bt[seq_at(seq, j + 3, is64) * NB + cc];
        }
#pragma unroll
        for (int r = 0; r < ROWS_PB; r++) {
            float4* rowp = chan + (size_t)(i0 + r) * row_f4;
#pragma unroll
            for (int k = 0; k < 4; k++) {
                __stcs(rowp + t + k * TPB, p[k]);
            }
        }
    }
}

extern "C" void kernel_launch(void* const* d_in, const int* in_sizes, int n_in,
                              void* d_out, int out_size) {
    const void*  seq = d_in[0];                 // 4096 ids (int32 or int64; auto-detected)
    const float* bt  = (const float*)d_in[1];   // 4x4 identity table, fp32
    float*       out = (float*)d_out;           // (1, 8, 4096, 4096) fp32

    const int total_rows = 8 * SEQ_L;                    // 32768
    const int grid = total_rows / ROWS_PB;               // 4096 blocks
    SequenceEmbedding_30923764532139_kernel<<<grid, TPB>>>(seq, bt, out);
}

// round 16
// speedup vs baseline: 1.5395x; 1.0183x over previous
#include <cuda_runtime.h>
#include <cuda_bf16.h>
#include <cstdint>

// SequenceEmbedding: out[0][c][i][j] = one_hot(seq[i])[c]          for c in [0,4)
//                    out[0][c][i][j] = one_hot(seq[j])[c-4]        for c in [4,8)
// Output (1, 8, 4096, 4096) fp32 = 536.9 MB of pure stores; HBM-write-bound.
//
// R15 = champion (R6/R14, 80.0us reproduced twice) with ONE change:
// 256-bit stores (st.global.cs.v8.b32) instead of STG.128 pairs. Halves
// STG instruction count / L1tex store-instruction slots; same sectors,
// same hint, same grid (4096 x 256, 8 rows/block, 6 blocks/SM).

#define SEQ_L   4096
#define NB      4
#define ROWS_PB 8           // rows per block
#define TPB     256         // threads per block

// Detect whether seq buffer is int64 or int32 (values in [0,4): odd 32-bit
// words of an int64 LE layout are all zero; FP prob 4^-64 for int32 data).
__device__ __forceinline__ bool seq_is_int64(const int* s32) {
    bool is64 = true;
#pragma unroll
    for (int k = 0; k < 64; k++) {
        if (s32[2 * k + 1] != 0) is64 = false;
    }
    return is64;
}

__device__ __forceinline__ int seq_at(const void* seq, int i, bool is64) {
    if (is64) return (int)((const long long*)seq)[i];
    return ((const int*)seq)[i];
}

// 256-bit streaming store (32B, address must be 32B-aligned).
__device__ __forceinline__ void st_cs_256(float4* p, float4 a, float4 b) {
    asm volatile(
        "st.global.cs.v8.b32 [%0], {%1,%2,%3,%4,%5,%6,%7,%8};"
        :: "l"(p),
           "r"(__float_as_uint(a.x)), "r"(__float_as_uint(a.y)),
           "r"(__float_as_uint(a.z)), "r"(__float_as_uint(a.w)),
           "r"(__float_as_uint(b.x)), "r"(__float_as_uint(b.y)),
           "r"(__float_as_uint(b.z)), "r"(__float_as_uint(b.w))
        : "memory");
}

__global__ void __launch_bounds__(TPB, 6)
SequenceEmbedding_30923764532139_kernel(const void* __restrict__ seq,
                                        const float* __restrict__ bt,
                                        float* __restrict__ out) {
    const int bx = blockIdx.x;
    const int c  = bx >> 9;                // 512 blocks per channel, 8 channels
    const int i0 = (bx & 511) * ROWS_PB;   // first row handled by this block
    const int t  = threadIdx.x;

    const bool is64 = seq_is_int64((const int*)seq);

    float4* __restrict__ chan = (float4*)(out + (size_t)c * SEQ_L * SEQ_L);
    const int row_f4 = SEQ_L / 4;          // 1024 float4 per row = 512 x 32B chunks

    if (c < NB) {
        // Row-splat channels: value constant along j, varies per row i.
#pragma unroll
        for (int r = 0; r < ROWS_PB; r++) {
            const int i = i0 + r;
            const float v = bt[seq_at(seq, i, is64) * NB + c];   // uniform, L1-hot
            const float4 vv = make_float4(v, v, v, v);
            float4* rowp = chan + (size_t)i * row_f4;
            // Two 32B chunks per thread: chunk indices t and t+TPB.
#pragma unroll
            for (int k = 0; k < 2; k++) {
                st_cs_256(rowp + 2 * (t + k * TPB), vv, vv);
            }
        }
    } else {
        // Column-pattern channels: every row of the channel is identical.
        // p[2k], p[2k+1] form the 32B chunk at index (t + k*TPB):
        // floats [8*(t+k*TPB), 8*(t+k*TPB)+8).
        const int cc = c - NB;
        float4 p[4];
#pragma unroll
        for (int k = 0; k < 4; k++) {
            const int j = 8 * (t + (k >> 1) * TPB) + (k & 1) * 4;
            p[k].x = bt[seq_at(seq, j + 0, is64) * NB + cc];
            p[k].y = bt[seq_at(seq, j + 1, is64) * NB + cc];
            p[k].z = bt[seq_at(seq, j + 2, is64) * NB + cc];
            p[k].w = bt[seq_at(seq, j + 3, is64) * NB + cc];
        }
#pragma unroll
        for (int r = 0; r < ROWS_PB; r++) {
            float4* rowp = chan + (size_t)(i0 + r) * row_f4;
#pragma unroll
            for (int k = 0; k < 2; k++) {
                st_cs_256(rowp + 2 * (t + k * TPB), p[2 * k], p[2 * k + 1]);
            }
        }
    }
}

extern "C" void kernel_launch(void* const* d_in, const int* in_sizes, int n_in,
                              void* d_out, int out_size) {
    const void*  seq = d_in[0];                 // 4096 ids (int32 or int64; auto-detected)
    const float* bt  = (const float*)d_in[1];   // 4x4 identity table, fp32
    float*       out = (float*)d_out;           // (1, 8, 4096, 4096) fp32

    const int total_rows = 8 * SEQ_L;                    // 32768
    const int grid = total_rows / ROWS_PB;               // 4096 blocks
    SequenceEmbedding_30923764532139_kernel<<<grid, TPB>>>(seq, bt, out);
}